// round 12
// baseline (speedup 1.0000x reference)
#include <cuda_runtime.h>
#include <math.h>

#define NMODES 64
#define LSEQ   262144
#define SEG    32
#define NSEGS  (LSEQ/SEG)        /* 8192 */

#define SCAN_T 1024
#define CPT    8                 /* segs per scan thread */
#define LEVELS 10                /* log2(SCAN_T) */

#define KC_CHUNK 16
#define KC_GRID  (NSEGS/KC_CHUNK) /* 512 */

// ---------------- scratch (static device globals; no allocation) ----------------
__device__ float  g_V[32 * 128];          // [k][row]  row: 0..63 re(z^(31-k)), 64..127 im
__device__ float  g_Mt[160 * 32];         // [K][t]    K<32: Toeplitz W (D folded); K>=32: carry proj
__device__ float  g_Pp[128 * NSEGS];      // planar P: rows 0..63 re, 64..127 im
__device__ float  g_Xc[128 * NSEGS];      // planar carries, same layout
__device__ float2 g_a32[NMODES];          // z^32
__device__ float2 g_mk2[NMODES * LEVELS]; // z^(256 * 2^k), k=0..9

// ---------------- fast z^e: double phase reduction + MUFU sin/cos ----------------
static __device__ __forceinline__ float2 cexp_pow(double dr, double di, double e) {
    float m = expf((float)(e * dr));
    double t = e * di;
    double q = rint(t * 0.15915494309189533576888376337251);
    double r = fma(q, -6.283185307179586476925286766559, t);
    float s, c;
    sincosf((float)r, &s, &c);
    return make_float2(m * c, m * s);
}

// ---------------- K0: constants + coefficient matrices, 512 threads ----------------
__global__ void __launch_bounds__(512) k0_setup(const float* __restrict__ A_re,
                                                const float* __restrict__ A_im,
                                                const float* __restrict__ C,
                                                const float* __restrict__ D,
                                                const float* __restrict__ log_step) {
    __shared__ float sW[32 * 64];
    __shared__ float sWl[32];
    int t = threadIdx.x;
    int m = t & 63, g = t >> 6;          // 64 modes x 8 groups
    double dt = exp((double)log_step[0]);
    double ar = (double)A_re[m], ai = (double)A_im[m];
    double dr = dt * ar, di = dt * ai;

    float2 z1 = cexp_pow(dr, di, 1.0);
    double ctr = (double)C[2 * m], cti = (double)C[2 * m + 1];
    double wr = (double)z1.x - 1.0, wi = (double)z1.y;
    double den = ar * ar + ai * ai;
    double qr = (wr * ar + wi * ai) / den;
    double qi = (wi * ar - wr * ai) / den;
    float cfr = (float)(ctr * qr - cti * qi);
    float cfi = (float)(ctr * qi + cti * qr);

    // V rows + W columns: exponents 4g..4g+3
#pragma unroll
    for (int j = 0; j < 4; j++) {
        int e = 4 * g + j;
        float2 w = cexp_pow(dr, di, (double)e);
        g_V[(31 - e) * 128 + m]      = w.x;
        g_V[(31 - e) * 128 + 64 + m] = w.y;
        sW[e * 64 + m] = cfr * w.x - cfi * w.y;       // Re(c z^e)
    }
    // carry projection rows: tr = 4g..4g+3
#pragma unroll
    for (int j = 0; j < 4; j++) {
        int tr = 4 * g + j;
        float2 w = cexp_pow(dr, di, (double)(tr + 1));
        g_Mt[(32 + m) * 32 + tr] = cfr * w.x - cfi * w.y;     // Re(c z^{t+1})
        g_Mt[(96 + m) * 32 + tr] = -(cfr * w.y + cfi * w.x);  // -Im(c z^{t+1})
    }
    if (g == 0) g_a32[m] = cexp_pow(dr, di, 32.0);
    if (g == 1) {
        double e = 256.0;
#pragma unroll
        for (int k = 0; k < LEVELS; k++) { g_mk2[m * LEVELS + k] = cexp_pow(dr, di, e); e *= 2.0; }
    }
    __syncthreads();
    if (t < 32) {
        float s = 0.f;
        for (int mm = 0; mm < 64; mm++) s += sW[t * 64 + mm];
        sWl[t] = s;                      // W[l] = Re sum_n c_n z_n^l
    }
    __syncthreads();
    float Dv = D[0];
    for (int idx = t; idx < 1024; idx += 512) {
        int k = idx >> 5, tt = idx & 31;
        float v = (tt >= k) ? sWl[tt - k] : 0.f;
        if (tt == k) v += Dv;            // fold D*u into the Toeplitz diagonal
        g_Mt[k * 32 + tt] = v;
    }
}

// ---------------- kA: P[128][8192] = V[128][32] @ U[32][8192], row/thread ----------------
// grid = 1024 blocks x 128 thr; block handles 8 segs (256 samples).
__global__ void __launch_bounds__(128) kA_pgemm(const float* __restrict__ u) {
    __shared__ float sV[4096];
    __shared__ float sU[32 * 12];        // stride 12: float4-aligned, conflict-light
    int t = threadIdx.x, c = blockIdx.x;
    {
        const float4* vs = (const float4*)g_V;
        float4* vd = (float4*)sV;
        for (int i = t; i < 1024; i += 128) vd[i] = vs[i];
    }
    const float* ub = u + c * 256;
    for (int i = t; i < 256; i += 128) {
        int seg = i >> 5, k = i & 31;
        sU[k * 12 + seg] = ub[i];
    }
    __syncthreads();

    float a0 = 0.f, a1 = 0.f, a2 = 0.f, a3 = 0.f;
    float a4 = 0.f, a5 = 0.f, a6 = 0.f, a7 = 0.f;
#pragma unroll
    for (int k = 0; k < 32; k++) {
        float  v  = sV[k * 128 + t];                 // conflict-free
        float4 u0 = *(const float4*)&sU[k * 12];     // broadcast
        float4 u1 = *(const float4*)&sU[k * 12 + 4]; // broadcast
        a0 = fmaf(v, u0.x, a0); a1 = fmaf(v, u0.y, a1);
        a2 = fmaf(v, u0.z, a2); a3 = fmaf(v, u0.w, a3);
        a4 = fmaf(v, u1.x, a4); a5 = fmaf(v, u1.y, a5);
        a6 = fmaf(v, u1.z, a6); a7 = fmaf(v, u1.w, a7);
    }
    float4* pr = (float4*)&g_Pp[t * NSEGS + c * 8];  // direct, 32B/thread
    pr[0] = make_float4(a0, a1, a2, a3);
    pr[1] = make_float4(a4, a5, a6, a7);
}

// ---------------- kB: per-mode fp32 scan over 8192 segs, emit carries ----------------
#define BSTEP(Er, Ei, pr, pi)                          \
    do {                                               \
        float _tr = fmaf(-a.y, (Ei), (pr));            \
        float _ti = fmaf( a.y, (Er), (pi));            \
        (Er) = fmaf(a.x, (Er), _tr);                   \
        (Ei) = fmaf(a.x, (Ei), _ti);                   \
    } while (0)

__global__ void __launch_bounds__(SCAN_T) kB_scan() {
    __shared__ float smr[SCAN_T];
    __shared__ float smi[SCAN_T];
    int n = blockIdx.x, t = threadIdx.x;
    float2 a = g_a32[n];
    const float* pre = &g_Pp[n * NSEGS];
    const float* pim = &g_Pp[(64 + n) * NSEGS];
    int s0 = t * CPT;

    float Br = 0.f, Bi = 0.f;
#pragma unroll
    for (int j = 0; j < CPT; j += 4) {
        float4 r4 = *(const float4*)&pre[s0 + j];
        float4 i4 = *(const float4*)&pim[s0 + j];
        BSTEP(Br, Bi, r4.x, i4.x);
        BSTEP(Br, Bi, r4.y, i4.y);
        BSTEP(Br, Bi, r4.z, i4.z);
        BSTEP(Br, Bi, r4.w, i4.w);
    }
    smr[t] = Br; smi[t] = Bi;
#pragma unroll
    for (int k = 0; k < LEVELS; k++) {
        int off = 1 << k;
        float2 mm = g_mk2[n * LEVELS + k];
        __syncthreads();
        float lr = 0.f, li = 0.f;
        if (t >= off) { lr = smr[t - off]; li = smi[t - off]; }
        __syncthreads();
        if (t >= off) {
            float nr = fmaf(mm.x, lr, fmaf(-mm.y, li, Br));
            float ni = fmaf(mm.x, li, fmaf( mm.y, lr, Bi));
            Br = nr; Bi = ni;
            smr[t] = Br; smi[t] = Bi;
        }
    }
    __syncthreads();
    float Er = 0.f, Ei = 0.f;
    if (t > 0) { Er = smr[t - 1]; Ei = smi[t - 1]; }
    float* xre = &g_Xc[n * NSEGS];
    float* xim = &g_Xc[(64 + n) * NSEGS];
#pragma unroll
    for (int j = 0; j < CPT; j += 4) {
        float4 r4 = *(const float4*)&pre[s0 + j];
        float4 i4 = *(const float4*)&pim[s0 + j];
        float4 orv, oiv;
        orv.x = Er; oiv.x = Ei; BSTEP(Er, Ei, r4.x, i4.x);
        orv.y = Er; oiv.y = Ei; BSTEP(Er, Ei, r4.y, i4.y);
        orv.z = Er; oiv.z = Ei; BSTEP(Er, Ei, r4.z, i4.z);
        orv.w = Er; oiv.w = Ei; BSTEP(Er, Ei, r4.w, i4.w);
        *(float4*)&xre[s0 + j] = orv;
        *(float4*)&xim[s0 + j] = oiv;
    }
}

// ---------------- kC: Y[32][8192] = Mt[160][32]^T @ [U;Xc], full K, exclusive y ----------------
// grid = 512 blocks (16 segs each) x 128 thr; thread = 1 row x 4 segs.
__global__ void __launch_bounds__(128) kC_ygemm(const float* __restrict__ u,
                                               float* __restrict__ y) {
    __shared__ float sMt[160 * 32];      // 20 KB
    __shared__ float sR[160 * 20];       // 12.8 KB, stride 20 (float4-aligned)
    int t = threadIdx.x, b = blockIdx.x;
    int ss = b * KC_CHUNK;

    {   // stage Mt (all 160 rows)
        const float4* src = (const float4*)g_Mt;
        float4* dst = (float4*)sMt;
        for (int i = t; i < 1280; i += 128) dst[i] = src[i];
    }
    // R rows 0..31 = U^T: R[k][seg] = u[(ss+seg)*32 + k]
    for (int i = t; i < 512; i += 128) {
        int seg = i >> 5, k = i & 31;
        sR[k * 20 + seg] = u[(ss + seg) * 32 + k];
    }
    // R rows 32..159 = Xc rows 0..127
    for (int i = t; i < 128 * KC_CHUNK; i += 128) {
        int r = i >> 4, s = i & 15;
        sR[(32 + r) * 20 + s] = g_Xc[r * NSEGS + ss + s];
    }
    __syncthreads();

    int row = t & 31, sg = t >> 5;       // row 0..31, seg group 0..3 (4 segs each)
    float a0 = 0.f, a1 = 0.f, a2 = 0.f, a3 = 0.f;
#pragma unroll 8
    for (int k = 0; k < 160; k++) {
        float  mv = sMt[k * 32 + row];                 // conflict-free LDS.32
        float4 rv = *(const float4*)&sR[k * 20 + 4 * sg]; // warp-broadcast LDS.128
        a0 = fmaf(mv, rv.x, a0);
        a1 = fmaf(mv, rv.y, a1);
        a2 = fmaf(mv, rv.z, a2);
        a3 = fmaf(mv, rv.w, a3);
    }
    y[(ss + 4 * sg + 0) * 32 + row] = a0;
    y[(ss + 4 * sg + 1) * 32 + row] = a1;
    y[(ss + 4 * sg + 2) * 32 + row] = a2;
    y[(ss + 4 * sg + 3) * 32 + row] = a3;
}

// ---------------- host ----------------
extern "C" void kernel_launch(void* const* d_in, const int* in_sizes, int n_in,
                              void* d_out, int out_size) {
    const float* u = 0; const float* A_re = 0; const float* A_im = 0;
    const float* C = 0; const float* D = 0; const float* log_step = 0;
    for (int i = 0; i < n_in; i++) {
        int sz = in_sizes[i];
        const float* p = (const float*)d_in[i];
        if (sz == LSEQ)            { if (!u) u = p; }
        else if (sz == 2 * NMODES) { if (!C) C = p; }
        else if (sz == NMODES)     { if (!A_re) A_re = p; else A_im = p; }
        else if (sz == 1)          { if (!D) D = p; else log_step = p; }
    }
    float* y = (float*)d_out;

    k0_setup<<<1, 512>>>(A_re, A_im, C, D, log_step);
    kA_pgemm<<<NSEGS / 8, 128>>>(u);
    kB_scan<<<NMODES, SCAN_T>>>();
    kC_ygemm<<<KC_GRID, 128>>>(u, y);
}

// round 13
// speedup vs baseline: 1.2005x; 1.2005x over previous
#include <cuda_runtime.h>
#include <math.h>

#define NMODES 64
#define LSEQ   262144
#define SEG    32
#define NSEGS  (LSEQ/SEG)        /* 8192 */

#define SCAN_T 1024
#define CPT    8                 /* segs per scan thread */
#define LEVELS 10                /* log2(SCAN_T) */

#define KC_CHUNK 16
#define KC_GRID  (NSEGS/KC_CHUNK) /* 512 */
#define RSTR     20              /* sR row stride: float4-aligned */

// ---------------- scratch (static device globals; no allocation) ----------------
__device__ float  g_V[32 * 128];          // [k][row]  row: 0..63 re(z^(31-k)), 64..127 im
__device__ float  g_Mt[160 * 32];         // [K][t]    K<32: Toeplitz W (D folded); K>=32: carry proj
__device__ float  g_Pp[128 * NSEGS];      // planar P: rows 0..63 re, 64..127 im
__device__ float  g_Xc[128 * NSEGS];      // planar carries, same layout
__device__ float2 g_a32[NMODES];          // z^32
__device__ float2 g_mk2[NMODES * LEVELS]; // z^(256 * 2^k), k=0..9

// ---------------- z^e, double phase (large e only) ----------------
static __device__ __forceinline__ float2 cexp_pow_d(double dr, double di, double e) {
    float m = expf((float)(e * dr));
    double t = e * di;
    double q = rint(t * 0.15915494309189533576888376337251);
    double r = fma(q, -6.283185307179586476925286766559, t);
    float s, c;
    sincosf((float)r, &s, &c);
    return make_float2(m * c, m * s);
}
// ---------------- z^e, fp32 phase (e <= 33: phase <= ~700 rad, err ~4e-5) ----------------
static __device__ __forceinline__ float2 cexp_pow_f(float dr, float di, float e) {
    float m = expf(e * dr);
    float t = e * di;
    float q = rintf(t * 0.15915494309189533576888376337251f);
    float r = fmaf(q, -6.283185307179586476925286766559f, t);
    float s, c;
    sincosf(r, &s, &c);
    return make_float2(m * c, m * s);
}

// ---------------- K0: constants + coefficient matrices, 512 threads ----------------
__global__ void __launch_bounds__(512) k0_setup(const float* __restrict__ A_re,
                                                const float* __restrict__ A_im,
                                                const float* __restrict__ C,
                                                const float* __restrict__ D,
                                                const float* __restrict__ log_step) {
    __shared__ float sW[32 * 64];
    __shared__ float sWl[32];
    int t = threadIdx.x;
    int m = t & 63, g = t >> 6;          // 64 modes x 8 groups
    double dt = exp((double)log_step[0]);
    double ar = (double)A_re[m], ai = (double)A_im[m];
    double dr = dt * ar, di = dt * ai;
    float fdr = (float)dr, fdi = (float)di;

    float2 z1 = cexp_pow_f(fdr, fdi, 1.0f);
    double ctr = (double)C[2 * m], cti = (double)C[2 * m + 1];
    double wr = (double)z1.x - 1.0, wi = (double)z1.y;
    double den = ar * ar + ai * ai;
    double qr = (wr * ar + wi * ai) / den;
    double qi = (wi * ar - wr * ai) / den;
    float cfr = (float)(ctr * qr - cti * qi);
    float cfi = (float)(ctr * qi + cti * qr);

    // V rows + W columns: exponents 4g..4g+3 (fp32 path)
#pragma unroll
    for (int j = 0; j < 4; j++) {
        int e = 4 * g + j;
        float2 w = cexp_pow_f(fdr, fdi, (float)e);
        g_V[(31 - e) * 128 + m]      = w.x;
        g_V[(31 - e) * 128 + 64 + m] = w.y;
        sW[e * 64 + m] = cfr * w.x - cfi * w.y;       // Re(c z^e)
    }
    // carry projection rows: tr = 4g..4g+3 (fp32 path, e <= 32)
#pragma unroll
    for (int j = 0; j < 4; j++) {
        int tr = 4 * g + j;
        float2 w = cexp_pow_f(fdr, fdi, (float)(tr + 1));
        g_Mt[(32 + m) * 32 + tr] = cfr * w.x - cfi * w.y;     // Re(c z^{t+1})
        g_Mt[(96 + m) * 32 + tr] = -(cfr * w.y + cfi * w.x);  // -Im(c z^{t+1})
    }
    if (g == 0) g_a32[m] = cexp_pow_f(fdr, fdi, 32.0f);
    if (g == 1) {                         // large exponents: double phase
        double e = 256.0;
#pragma unroll
        for (int k = 0; k < LEVELS; k++) { g_mk2[m * LEVELS + k] = cexp_pow_d(dr, di, e); e *= 2.0; }
    }
    __syncthreads();
    if (t < 32) {
        float s = 0.f;
        for (int mm = 0; mm < 64; mm++) s += sW[t * 64 + mm];
        sWl[t] = s;                      // W[l] = Re sum_n c_n z_n^l
    }
    __syncthreads();
    float Dv = D[0];
    for (int idx = t; idx < 1024; idx += 512) {
        int k = idx >> 5, tt = idx & 31;
        float v = (tt >= k) ? sWl[tt - k] : 0.f;
        if (tt == k) v += Dv;            // fold D*u into the Toeplitz diagonal
        g_Mt[k * 32 + tt] = v;
    }
}

// ---------------- kA: P[128][8192] = V[128][32] @ U[32][8192], row/thread ----------------
// grid = 1024 blocks x 128 thr; block handles 8 segs (256 samples).
__global__ void __launch_bounds__(128) kA_pgemm(const float* __restrict__ u) {
    __shared__ float sV[4096];
    __shared__ float sU[32 * 12];        // stride 12: float4-aligned, conflict-light
    int t = threadIdx.x, c = blockIdx.x;
    {
        const float4* vs = (const float4*)g_V;
        float4* vd = (float4*)sV;
        for (int i = t; i < 1024; i += 128) vd[i] = vs[i];
    }
    const float* ub = u + c * 256;
    for (int i = t; i < 256; i += 128) {
        int seg = i >> 5, k = i & 31;
        sU[k * 12 + seg] = ub[i];
    }
    __syncthreads();

    float a0 = 0.f, a1 = 0.f, a2 = 0.f, a3 = 0.f;
    float a4 = 0.f, a5 = 0.f, a6 = 0.f, a7 = 0.f;
#pragma unroll
    for (int k = 0; k < 32; k++) {
        float  v  = sV[k * 128 + t];                 // conflict-free
        float4 u0 = *(const float4*)&sU[k * 12];     // broadcast
        float4 u1 = *(const float4*)&sU[k * 12 + 4]; // broadcast
        a0 = fmaf(v, u0.x, a0); a1 = fmaf(v, u0.y, a1);
        a2 = fmaf(v, u0.z, a2); a3 = fmaf(v, u0.w, a3);
        a4 = fmaf(v, u1.x, a4); a5 = fmaf(v, u1.y, a5);
        a6 = fmaf(v, u1.z, a6); a7 = fmaf(v, u1.w, a7);
    }
    float4* pr = (float4*)&g_Pp[t * NSEGS + c * 8];  // direct, 32B/thread
    pr[0] = make_float4(a0, a1, a2, a3);
    pr[1] = make_float4(a4, a5, a6, a7);
}

// ---------------- kB: per-mode fp32 scan over 8192 segs, emit carries ----------------
#define BSTEP(Er, Ei, pr, pi)                          \
    do {                                               \
        float _tr = fmaf(-a.y, (Ei), (pr));            \
        float _ti = fmaf( a.y, (Er), (pi));            \
        (Er) = fmaf(a.x, (Er), _tr);                   \
        (Ei) = fmaf(a.x, (Ei), _ti);                   \
    } while (0)

__global__ void __launch_bounds__(SCAN_T) kB_scan() {
    __shared__ float smr[SCAN_T];
    __shared__ float smi[SCAN_T];
    int n = blockIdx.x, t = threadIdx.x;
    float2 a = g_a32[n];
    const float* pre = &g_Pp[n * NSEGS];
    const float* pim = &g_Pp[(64 + n) * NSEGS];
    int s0 = t * CPT;

    float Br = 0.f, Bi = 0.f;
#pragma unroll
    for (int j = 0; j < CPT; j += 4) {
        float4 r4 = *(const float4*)&pre[s0 + j];
        float4 i4 = *(const float4*)&pim[s0 + j];
        BSTEP(Br, Bi, r4.x, i4.x);
        BSTEP(Br, Bi, r4.y, i4.y);
        BSTEP(Br, Bi, r4.z, i4.z);
        BSTEP(Br, Bi, r4.w, i4.w);
    }
    smr[t] = Br; smi[t] = Bi;
#pragma unroll
    for (int k = 0; k < LEVELS; k++) {
        int off = 1 << k;
        float2 mm = g_mk2[n * LEVELS + k];
        __syncthreads();
        float lr = 0.f, li = 0.f;
        if (t >= off) { lr = smr[t - off]; li = smi[t - off]; }
        __syncthreads();
        if (t >= off) {
            float nr = fmaf(mm.x, lr, fmaf(-mm.y, li, Br));
            float ni = fmaf(mm.x, li, fmaf( mm.y, lr, Bi));
            Br = nr; Bi = ni;
            smr[t] = Br; smi[t] = Bi;
        }
    }
    __syncthreads();
    float Er = 0.f, Ei = 0.f;
    if (t > 0) { Er = smr[t - 1]; Ei = smi[t - 1]; }
    float* xre = &g_Xc[n * NSEGS];
    float* xim = &g_Xc[(64 + n) * NSEGS];
#pragma unroll
    for (int j = 0; j < CPT; j += 4) {
        float4 r4 = *(const float4*)&pre[s0 + j];
        float4 i4 = *(const float4*)&pim[s0 + j];
        float4 orv, oiv;
        orv.x = Er; oiv.x = Ei; BSTEP(Er, Ei, r4.x, i4.x);
        orv.y = Er; oiv.y = Ei; BSTEP(Er, Ei, r4.y, i4.y);
        orv.z = Er; oiv.z = Ei; BSTEP(Er, Ei, r4.z, i4.z);
        orv.w = Er; oiv.w = Ei; BSTEP(Er, Ei, r4.w, i4.w);
        *(float4*)&xre[s0 + j] = orv;
        *(float4*)&xim[s0 + j] = oiv;
    }
}

// ---------------- kC: Y = Mt^T @ [U;Xc], K-split across warps, 16 acc/thread ----------------
// grid = 512 blocks (16 segs each) x 128 thr.
// Warp w handles k in [40w, 40w+40); thread: row = lane, 16 segs of accumulators.
__global__ void __launch_bounds__(128) kC_ygemm(const float* __restrict__ u,
                                               float* __restrict__ y) {
    __shared__ float sMt[160 * 32];      // 20 KB
    __shared__ float sR[160 * RSTR];     // 12.8 KB
    __shared__ float sRed[4 * 512];      // 8 KB: [warp][seg*32+row]
    int t = threadIdx.x, b = blockIdx.x;
    int ss = b * KC_CHUNK;

    {   // stage Mt (all 160 rows), coalesced float4
        const float4* src = (const float4*)g_Mt;
        float4* dst = (float4*)sMt;
        for (int i = t; i < 1280; i += 128) dst[i] = src[i];
    }
    // R rows 0..31 = U^T: contiguous gmem read, transposed smem write
    for (int i = t; i < 512; i += 128) {
        int seg = i >> 5, k = i & 31;
        sR[k * RSTR + seg] = u[ss * 32 + i];
    }
    // R rows 32..159 = Xc rows 0..127, float4 both sides
    for (int i = t; i < 512; i += 128) {
        int r = i >> 2, c4 = i & 3;
        float4 v = *(const float4*)&g_Xc[r * NSEGS + ss + 4 * c4];
        *(float4*)&sR[(32 + r) * RSTR + 4 * c4] = v;
    }
    __syncthreads();

    int lane = t & 31, w = t >> 5;
    int k0 = w * 40;
    float acc[16];
#pragma unroll
    for (int j = 0; j < 16; j++) acc[j] = 0.f;

#pragma unroll 8
    for (int kk = 0; kk < 40; kk++) {
        int k = k0 + kk;
        float  mv  = sMt[k * 32 + lane];                  // conflict-free LDS.32
        float4 r0  = *(const float4*)&sR[k * RSTR];       // broadcasts
        float4 r1  = *(const float4*)&sR[k * RSTR + 4];
        float4 r2  = *(const float4*)&sR[k * RSTR + 8];
        float4 r3  = *(const float4*)&sR[k * RSTR + 12];
        acc[0]  = fmaf(mv, r0.x, acc[0]);  acc[1]  = fmaf(mv, r0.y, acc[1]);
        acc[2]  = fmaf(mv, r0.z, acc[2]);  acc[3]  = fmaf(mv, r0.w, acc[3]);
        acc[4]  = fmaf(mv, r1.x, acc[4]);  acc[5]  = fmaf(mv, r1.y, acc[5]);
        acc[6]  = fmaf(mv, r1.z, acc[6]);  acc[7]  = fmaf(mv, r1.w, acc[7]);
        acc[8]  = fmaf(mv, r2.x, acc[8]);  acc[9]  = fmaf(mv, r2.y, acc[9]);
        acc[10] = fmaf(mv, r2.z, acc[10]); acc[11] = fmaf(mv, r2.w, acc[11]);
        acc[12] = fmaf(mv, r3.x, acc[12]); acc[13] = fmaf(mv, r3.y, acc[13]);
        acc[14] = fmaf(mv, r3.z, acc[14]); acc[15] = fmaf(mv, r3.w, acc[15]);
    }
    // dump per-warp partials (conflict-free: addr = lane + 32*seg)
#pragma unroll
    for (int j = 0; j < 16; j++) sRed[w * 512 + j * 32 + lane] = acc[j];
    __syncthreads();

    // combine 4 K-quarters, coalesced y write
    for (int i = t; i < 512; i += 128) {
        float s = (sRed[i] + sRed[512 + i]) + (sRed[1024 + i] + sRed[1536 + i]);
        y[ss * 32 + i] = s;
    }
}

// ---------------- host ----------------
extern "C" void kernel_launch(void* const* d_in, const int* in_sizes, int n_in,
                              void* d_out, int out_size) {
    const float* u = 0; const float* A_re = 0; const float* A_im = 0;
    const float* C = 0; const float* D = 0; const float* log_step = 0;
    for (int i = 0; i < n_in; i++) {
        int sz = in_sizes[i];
        const float* p = (const float*)d_in[i];
        if (sz == LSEQ)            { if (!u) u = p; }
        else if (sz == 2 * NMODES) { if (!C) C = p; }
        else if (sz == NMODES)     { if (!A_re) A_re = p; else A_im = p; }
        else if (sz == 1)          { if (!D) D = p; else log_step = p; }
    }
    float* y = (float*)d_out;

    k0_setup<<<1, 512>>>(A_re, A_im, C, D, log_step);
    kA_pgemm<<<NSEGS / 8, 128>>>(u);
    kB_scan<<<NMODES, SCAN_T>>>();
    kC_ygemm<<<KC_GRID, 128>>>(u, y);
}

// round 14
// speedup vs baseline: 1.8290x; 1.5236x over previous
#include <cuda_runtime.h>
#include <math.h>

#define NMODES 64
#define LSEQ   262144
#define NSEGS  8192              /* segments of 32 samples */
#define SCAN_T 1024
#define CPT    8                 /* segs per scan thread */
#define LEVELS 10                /* log2(SCAN_T) */

#define KA_GRID 512
#define KA_THR  256
#define KC_GRID 512
#define KC_THR  256
#define KC_CHUNK 16
#define RSTR    20               /* sR row stride, float4-aligned */

// ---------------- scratch (static device globals; no allocation) ----------------
__device__ float g_Mt[160 * 32];     // [K][t] K<32: Toeplitz W (D folded); K>=32: carry proj
__device__ float g_Pp[128 * NSEGS];  // planar P: rows 0..63 re, 64..127 im
__device__ float g_Xc[128 * NSEGS];  // planar carries, same layout

// ---------------- z^e, double phase (large e) ----------------
static __device__ __forceinline__ float2 cexp_pow_d(double dr, double di, double e) {
    float m = expf((float)(e * dr));
    double t = e * di;
    double q = rint(t * 0.15915494309189533576888376337251);
    double r = fma(q, -6.283185307179586476925286766559, t);
    float s, c;
    sincosf((float)r, &s, &c);
    return make_float2(m * c, m * s);
}
// ---------------- z^e, fp32 phase (e <= 33; verified in R13) ----------------
static __device__ __forceinline__ float2 cexp_pow_f(float dr, float di, float e) {
    float m = expf(e * dr);
    float t = e * di;
    float q = rintf(t * 0.15915494309189533576888376337251f);
    float r = fmaf(q, -6.283185307179586476925286766559f, t);
    float s, c;
    sincosf(r, &s, &c);
    return make_float2(m * c, m * s);
}

// ---------------- kA: P[128][8192] = V @ U, V generated in registers ----------------
// grid = 512 blocks x 256 thr; block covers 16 segs (512 samples).
// Thread: row r = t&127 (mode m=r&63, part=r>>6), seg-half h = t>>7 (8 segs).
// Block 0 additionally builds g_Mt (Toeplitz + carry projection), all fp32.
__global__ void __launch_bounds__(KA_THR) kA_pgemm(const float* __restrict__ u,
                                                   const float* __restrict__ A_re,
                                                   const float* __restrict__ A_im,
                                                   const float* __restrict__ C,
                                                   const float* __restrict__ D,
                                                   const float* __restrict__ log_step) {
    __shared__ float sU[32 * 16];    // [k][seg] 2 KB
    __shared__ float sW[32 * 64];    // block 0 only
    __shared__ float sWl[32];
    int t = threadIdx.x, c = blockIdx.x;
    int r = t & 127, h = t >> 7;
    int m = r & 63, part = r >> 6;

    const float* ub = u + c * 512;
    for (int i = t; i < 512; i += KA_THR)
        sU[(i & 31) * 16 + (i >> 5)] = ub[i];

    float dtf = expf(log_step[0]);
    float fdr = dtf * A_re[m], fdi = dtf * A_im[m];
    float2 z = cexp_pow_f(fdr, fdi, 1.0f);
    __syncthreads();

    float a0 = 0.f, a1 = 0.f, a2 = 0.f, a3 = 0.f;
    float a4 = 0.f, a5 = 0.f, a6 = 0.f, a7 = 0.f;
    float wx = 1.f, wy = 0.f;        // z^e, e ascending; k = 31-e (sum order free)
#pragma unroll
    for (int e = 0; e < 32; e++) {
        int k = 31 - e;
        float v = part ? wy : wx;
        float4 u0 = *(const float4*)&sU[k * 16 + 8 * h];       // broadcast
        float4 u1 = *(const float4*)&sU[k * 16 + 8 * h + 4];   // broadcast
        a0 = fmaf(v, u0.x, a0); a1 = fmaf(v, u0.y, a1);
        a2 = fmaf(v, u0.z, a2); a3 = fmaf(v, u0.w, a3);
        a4 = fmaf(v, u1.x, a4); a5 = fmaf(v, u1.y, a5);
        a6 = fmaf(v, u1.z, a6); a7 = fmaf(v, u1.w, a7);
        float nwx = fmaf(wx, z.x, -(wy * z.y));
        float nwy = fmaf(wx, z.y, wy * z.x);
        wx = nwx; wy = nwy;
    }
    float4* pr = (float4*)&g_Pp[r * NSEGS + c * 16 + 8 * h];
    pr[0] = make_float4(a0, a1, a2, a3);
    pr[1] = make_float4(a4, a5, a6, a7);

    if (c == 0) {                    // build Mt (runs concurrent with other 511 blocks)
        __syncthreads();
        // coeff = Ct * (z - 1) / A, fp32
        float ar = A_re[m], ai = A_im[m];
        float ctr = C[2 * m], cti = C[2 * m + 1];
        float wr = z.x - 1.f, wi = z.y;
        float den = ar * ar + ai * ai;
        float qr = (wr * ar + wi * ai) / den;
        float qi = (wi * ar - wr * ai) / den;
        float cfr = ctr * qr - cti * qi;
        float cfi = ctr * qi + cti * qr;
        int g = t >> 6;              // 0..3, 8 exponents each
#pragma unroll
        for (int j = 0; j < 8; j++) {
            int e = 8 * g + j;
            float2 we = cexp_pow_f(fdr, fdi, (float)e);
            sW[e * 64 + m] = cfr * we.x - cfi * we.y;             // Re(c z^e)
            float2 w1 = cexp_pow_f(fdr, fdi, (float)(e + 1));
            g_Mt[(32 + m) * 32 + e] = cfr * w1.x - cfi * w1.y;    // Re(c z^{t+1})
            g_Mt[(96 + m) * 32 + e] = -(cfr * w1.y + cfi * w1.x); // -Im(c z^{t+1})
        }
        __syncthreads();
        if (t < 32) {
            float s = 0.f;
            for (int mm = 0; mm < 64; mm++) s += sW[t * 64 + mm];
            sWl[t] = s;              // W[l] = Re sum_n c_n z_n^l
        }
        __syncthreads();
        float Dv = D[0];
        for (int idx = t; idx < 1024; idx += KA_THR) {
            int k = idx >> 5, tt = idx & 31;
            float v = (tt >= k) ? sWl[tt - k] : 0.f;
            if (tt == k) v += Dv;    // fold D*u into Toeplitz diagonal
            g_Mt[k * 32 + tt] = v;
        }
    }
}

// ---------------- kB: per-mode fp32 scan over 8192 segs, emit carries ----------------
#define BSTEP(Er, Ei, pr, pi)                          \
    do {                                               \
        float _tr = fmaf(-a.y, (Ei), (pr));            \
        float _ti = fmaf( a.y, (Er), (pi));            \
        (Er) = fmaf(a.x, (Er), _tr);                   \
        (Ei) = fmaf(a.x, (Ei), _ti);                   \
    } while (0)

__global__ void __launch_bounds__(SCAN_T) kB_scan(const float* __restrict__ A_re,
                                                  const float* __restrict__ A_im,
                                                  const float* __restrict__ log_step) {
    __shared__ float smr[SCAN_T];
    __shared__ float smi[SCAN_T];
    __shared__ float2 s_mul[LEVELS + 1];   // [0..9] = KS multipliers, [10] = z^32
    int n = blockIdx.x, t = threadIdx.x;
    if (t <= LEVELS) {                     // self-compute constants (double phase)
        double dt = exp((double)log_step[0]);
        double dr = dt * (double)A_re[n], di = dt * (double)A_im[n];
        double e = (t == LEVELS) ? 32.0 : 256.0 * (double)(1 << t);
        s_mul[t] = cexp_pow_d(dr, di, e);
    }
    __syncthreads();
    float2 a = s_mul[LEVELS];
    const float* pre = &g_Pp[n * NSEGS];
    const float* pim = &g_Pp[(64 + n) * NSEGS];
    int s0 = t * CPT;

    float Br = 0.f, Bi = 0.f;
#pragma unroll
    for (int j = 0; j < CPT; j += 4) {
        float4 r4 = *(const float4*)&pre[s0 + j];
        float4 i4 = *(const float4*)&pim[s0 + j];
        BSTEP(Br, Bi, r4.x, i4.x);
        BSTEP(Br, Bi, r4.y, i4.y);
        BSTEP(Br, Bi, r4.z, i4.z);
        BSTEP(Br, Bi, r4.w, i4.w);
    }
    smr[t] = Br; smi[t] = Bi;
#pragma unroll
    for (int k = 0; k < LEVELS; k++) {
        int off = 1 << k;
        float2 mm = s_mul[k];
        __syncthreads();
        float lr = 0.f, li = 0.f;
        if (t >= off) { lr = smr[t - off]; li = smi[t - off]; }
        __syncthreads();
        if (t >= off) {
            float nr = fmaf(mm.x, lr, fmaf(-mm.y, li, Br));
            float ni = fmaf(mm.x, li, fmaf( mm.y, lr, Bi));
            Br = nr; Bi = ni;
            smr[t] = Br; smi[t] = Bi;
        }
    }
    __syncthreads();
    float Er = 0.f, Ei = 0.f;
    if (t > 0) { Er = smr[t - 1]; Ei = smi[t - 1]; }
    float* xre = &g_Xc[n * NSEGS];
    float* xim = &g_Xc[(64 + n) * NSEGS];
#pragma unroll
    for (int j = 0; j < CPT; j += 4) {
        float4 r4 = *(const float4*)&pre[s0 + j];
        float4 i4 = *(const float4*)&pim[s0 + j];
        float4 orv, oiv;
        orv.x = Er; oiv.x = Ei; BSTEP(Er, Ei, r4.x, i4.x);
        orv.y = Er; oiv.y = Ei; BSTEP(Er, Ei, r4.y, i4.y);
        orv.z = Er; oiv.z = Ei; BSTEP(Er, Ei, r4.z, i4.z);
        orv.w = Er; oiv.w = Ei; BSTEP(Er, Ei, r4.w, i4.w);
        *(float4*)&xre[s0 + j] = orv;
        *(float4*)&xim[s0 + j] = oiv;
    }
}

// ---------------- kC: Y = Mt^T @ [U;Xc], 8-warp K-split, 16 acc/thread ----------------
// grid = 512 blocks (16 segs) x 256 thr. Warp w: k in [20w, 20w+20); thread: row=lane.
// Reduction buffer aliases sMt (dead after the k-loop) -> 33 KB smem, 6 blocks/SM.
__global__ void __launch_bounds__(KC_THR) kC_ygemm(const float* __restrict__ u,
                                                   float* __restrict__ y) {
    __shared__ float sMt[160 * 32];      // 20 KB; reused as sRed[8*512] (16 KB) after compute
    __shared__ float sR[160 * RSTR];     // 12.8 KB
    int t = threadIdx.x, b = blockIdx.x;
    int ss = b * KC_CHUNK;

    {   // stage Mt, coalesced float4
        const float4* src = (const float4*)g_Mt;
        float4* dst = (float4*)sMt;
        for (int i = t; i < 1280; i += KC_THR) dst[i] = src[i];
    }
    // R rows 0..31 = U^T
    for (int i = t; i < 512; i += KC_THR) {
        int seg = i >> 5, k = i & 31;
        sR[k * RSTR + seg] = u[ss * 32 + i];
    }
    // R rows 32..159 = Xc rows 0..127, float4 both sides
    for (int i = t; i < 512; i += KC_THR) {
        int rr = i >> 2, c4 = i & 3;
        float4 v = *(const float4*)&g_Xc[rr * NSEGS + ss + 4 * c4];
        *(float4*)&sR[(32 + rr) * RSTR + 4 * c4] = v;
    }
    __syncthreads();

    int lane = t & 31, w = t >> 5;       // 8 warps
    int kbase = w * 20;
    float acc[16];
#pragma unroll
    for (int j = 0; j < 16; j++) acc[j] = 0.f;
#pragma unroll 5
    for (int kk = 0; kk < 20; kk++) {
        int k = kbase + kk;
        float  mv = sMt[k * 32 + lane];                 // conflict-free LDS.32
        float4 r0 = *(const float4*)&sR[k * RSTR];      // broadcasts
        float4 r1 = *(const float4*)&sR[k * RSTR + 4];
        float4 r2 = *(const float4*)&sR[k * RSTR + 8];
        float4 r3 = *(const float4*)&sR[k * RSTR + 12];
        acc[0]  = fmaf(mv, r0.x, acc[0]);  acc[1]  = fmaf(mv, r0.y, acc[1]);
        acc[2]  = fmaf(mv, r0.z, acc[2]);  acc[3]  = fmaf(mv, r0.w, acc[3]);
        acc[4]  = fmaf(mv, r1.x, acc[4]);  acc[5]  = fmaf(mv, r1.y, acc[5]);
        acc[6]  = fmaf(mv, r1.z, acc[6]);  acc[7]  = fmaf(mv, r1.w, acc[7]);
        acc[8]  = fmaf(mv, r2.x, acc[8]);  acc[9]  = fmaf(mv, r2.y, acc[9]);
        acc[10] = fmaf(mv, r2.z, acc[10]); acc[11] = fmaf(mv, r2.w, acc[11]);
        acc[12] = fmaf(mv, r3.x, acc[12]); acc[13] = fmaf(mv, r3.y, acc[13]);
        acc[14] = fmaf(mv, r3.z, acc[14]); acc[15] = fmaf(mv, r3.w, acc[15]);
    }
    __syncthreads();                     // everyone done READING sMt
    float* sRed = sMt;                   // alias: 8*512 floats
#pragma unroll
    for (int j = 0; j < 16; j++) sRed[w * 512 + j * 32 + lane] = acc[j];
    __syncthreads();

    for (int i = t; i < 512; i += KC_THR) {   // fixed-order 8-way sum, coalesced write
        float s = ((sRed[i]          + sRed[512 + i])  + (sRed[1024 + i] + sRed[1536 + i]))
                + ((sRed[2048 + i]   + sRed[2560 + i]) + (sRed[3072 + i] + sRed[3584 + i]));
        y[ss * 32 + i] = s;
    }
}

// ---------------- host: 3 kernel nodes ----------------
extern "C" void kernel_launch(void* const* d_in, const int* in_sizes, int n_in,
                              void* d_out, int out_size) {
    const float* u = 0; const float* A_re = 0; const float* A_im = 0;
    const float* C = 0; const float* D = 0; const float* log_step = 0;
    for (int i = 0; i < n_in; i++) {
        int sz = in_sizes[i];
        const float* p = (const float*)d_in[i];
        if (sz == LSEQ)            { if (!u) u = p; }
        else if (sz == 2 * NMODES) { if (!C) C = p; }
        else if (sz == NMODES)     { if (!A_re) A_re = p; else A_im = p; }
        else if (sz == 1)          { if (!D) D = p; else log_step = p; }
    }
    float* y = (float*)d_out;

    kA_pgemm<<<KA_GRID, KA_THR>>>(u, A_re, A_im, C, D, log_step);
    kB_scan<<<NMODES, SCAN_T>>>(A_re, A_im, log_step);
    kC_ygemm<<<KC_GRID, KC_THR>>>(u, y);
}

// round 15
// speedup vs baseline: 1.9783x; 1.0816x over previous
#include <cuda_runtime.h>
#include <math.h>

#define NMODES 64
#define LSEQ   262144
#define NSEGS  8192              /* segments of 32 samples */
#define SCAN_T 1024
#define CPT    8                 /* segs per scan thread */
#define LEVELS 10                /* log2(SCAN_T) */

#define KA_GRID 1024
#define KA_THR  128
#define KC_GRID 512
#define KC_THR  256
#define KC_CHUNK 16
#define RSTR    20               /* sR row stride, float4-aligned */

// ---------------- scratch (static device globals; no allocation) ----------------
__device__ float g_Mt[160 * 32];     // [K][t] K<32: Toeplitz W (D folded); K>=32: carry proj
__device__ float g_Pp[128 * NSEGS];  // planar P: rows 0..63 re, 64..127 im
__device__ float g_Xc[128 * NSEGS];  // planar carries, same layout

// ---------------- z^e, double phase (large e) ----------------
static __device__ __forceinline__ float2 cexp_pow_d(double dr, double di, double e) {
    float m = expf((float)(e * dr));
    double t = e * di;
    double q = rint(t * 0.15915494309189533576888376337251);
    double r = fma(q, -6.283185307179586476925286766559, t);
    float s, c;
    sincosf((float)r, &s, &c);
    return make_float2(m * c, m * s);
}
// ---------------- z^e, fp32 phase (e <= 33; verified R13/R14) ----------------
static __device__ __forceinline__ float2 cexp_pow_f(float dr, float di, float e) {
    float m = expf(e * dr);
    float t = e * di;
    float q = rintf(t * 0.15915494309189533576888376337251f);
    float r = fmaf(q, -6.283185307179586476925286766559f, t);
    float s, c;
    sincosf(r, &s, &c);
    return make_float2(m * c, m * s);
}

// ---------------- kA: P[128][8192] = V @ U, V precomputed in registers ----------------
// grid = 1024 blocks x 128 thr; block covers 8 segs (256 samples).
// Thread = one P row (mode m = t&63, part = t>>6). Inner loop: 2 LDS.128 + 8 FFMA.
__global__ void __launch_bounds__(KA_THR) kA_pgemm(const float* __restrict__ u,
                                                   const float* __restrict__ A_re,
                                                   const float* __restrict__ A_im,
                                                   const float* __restrict__ log_step) {
    __shared__ float sU[32 * 8];     // [k][seg] 1 KB
    int t = threadIdx.x, c = blockIdx.x;
    int m = t & 63, part = t >> 6;

    const float* ub = u + c * 256;
    for (int i = t; i < 256; i += KA_THR)
        sU[(i & 31) * 8 + (i >> 5)] = ub[i];

    float dtf = expf(log_step[0]);
    float fdr = dtf * A_re[m], fdi = dtf * A_im[m];
    float2 z = cexp_pow_f(fdr, fdi, 1.0f);

    // vv[e] = part ? Im(z^e) : Re(z^e)  (serial chain isolated from FMA stream)
    float vv[32];
    {
        float wx = 1.f, wy = 0.f;
#pragma unroll
        for (int e = 0; e < 32; e++) {
            vv[e] = part ? wy : wx;
            float nx = fmaf(wx, z.x, -(wy * z.y));
            float ny = fmaf(wx, z.y, wy * z.x);
            wx = nx; wy = ny;
        }
    }
    __syncthreads();

    float a0 = 0.f, a1 = 0.f, a2 = 0.f, a3 = 0.f;
    float a4 = 0.f, a5 = 0.f, a6 = 0.f, a7 = 0.f;
#pragma unroll
    for (int e = 0; e < 32; e++) {
        const int k = 31 - e;                       // compile-time
        float  v  = vv[e];
        float4 u0 = *(const float4*)&sU[k * 8];     // warp-uniform broadcast
        float4 u1 = *(const float4*)&sU[k * 8 + 4];
        a0 = fmaf(v, u0.x, a0); a1 = fmaf(v, u0.y, a1);
        a2 = fmaf(v, u0.z, a2); a3 = fmaf(v, u0.w, a3);
        a4 = fmaf(v, u1.x, a4); a5 = fmaf(v, u1.y, a5);
        a6 = fmaf(v, u1.z, a6); a7 = fmaf(v, u1.w, a7);
    }
    float4* pr = (float4*)&g_Pp[t * NSEGS + c * 8];
    pr[0] = make_float4(a0, a1, a2, a3);
    pr[1] = make_float4(a4, a5, a6, a7);
}

// ---------------- kB: per-mode fp32 scan; block 0 also builds g_Mt ----------------
#define BSTEP(Er, Ei, pr, pi)                          \
    do {                                               \
        float _tr = fmaf(-a.y, (Ei), (pr));            \
        float _ti = fmaf( a.y, (Er), (pi));            \
        (Er) = fmaf(a.x, (Er), _tr);                   \
        (Ei) = fmaf(a.x, (Ei), _ti);                   \
    } while (0)

__global__ void __launch_bounds__(SCAN_T) kB_scan(const float* __restrict__ A_re,
                                                  const float* __restrict__ A_im,
                                                  const float* __restrict__ C,
                                                  const float* __restrict__ D,
                                                  const float* __restrict__ log_step) {
    __shared__ float smr[SCAN_T];
    __shared__ float smi[SCAN_T];
    __shared__ float sW[32 * 64];          // block 0 Mt build
    __shared__ float sWl[32];
    __shared__ float2 s_mul[LEVELS + 1];   // [0..9] KS multipliers, [10] z^32
    int n = blockIdx.x, t = threadIdx.x;

    // ---- block 0: build Mt (Toeplitz + carry projection), fp32 path ----
    if (n == 0 && t < 256) {
        int m = t & 63, g = t >> 6;        // 4 groups x 8 exponents
        float dtf = expf(log_step[0]);
        float fdr = dtf * A_re[m], fdi = dtf * A_im[m];
        float2 z = cexp_pow_f(fdr, fdi, 1.0f);
        float ar = A_re[m], ai = A_im[m];
        float ctr = C[2 * m], cti = C[2 * m + 1];
        float wr = z.x - 1.f, wi = z.y;
        float den = ar * ar + ai * ai;
        float qr = (wr * ar + wi * ai) / den;
        float qi = (wi * ar - wr * ai) / den;
        float cfr = ctr * qr - cti * qi;
        float cfi = ctr * qi + cti * qr;
#pragma unroll
        for (int j = 0; j < 8; j++) {
            int e = 8 * g + j;
            float2 we = cexp_pow_f(fdr, fdi, (float)e);
            sW[e * 64 + m] = cfr * we.x - cfi * we.y;             // Re(c z^e)
            float2 w1 = cexp_pow_f(fdr, fdi, (float)(e + 1));
            g_Mt[(32 + m) * 32 + e] = cfr * w1.x - cfi * w1.y;    // Re(c z^{t+1})
            g_Mt[(96 + m) * 32 + e] = -(cfr * w1.y + cfi * w1.x); // -Im(c z^{t+1})
        }
    }
    if (t <= LEVELS) {                     // per-block scan constants (double phase)
        double dt = exp((double)log_step[0]);
        double dr = dt * (double)A_re[n], di = dt * (double)A_im[n];
        double e = (t == LEVELS) ? 32.0 : 256.0 * (double)(1 << t);
        s_mul[t] = cexp_pow_d(dr, di, e);
    }
    __syncthreads();
    if (n == 0 && t < 32) {
        float s = 0.f;
        for (int mm = 0; mm < 64; mm++) s += sW[t * 64 + mm];
        sWl[t] = s;                        // W[l] = Re sum_n c_n z_n^l
    }
    __syncthreads();
    if (n == 0 && t < 1024) {
        int k = t >> 5, tt = t & 31;
        float v = (tt >= k) ? sWl[tt - k] : 0.f;
        if (tt == k) v += D[0];            // fold D*u into Toeplitz diagonal
        g_Mt[k * 32 + tt] = v;
    }

    // ---- scan (verified body) ----
    float2 a = s_mul[LEVELS];
    const float* pre = &g_Pp[n * NSEGS];
    const float* pim = &g_Pp[(64 + n) * NSEGS];
    int s0 = t * CPT;

    float Br = 0.f, Bi = 0.f;
#pragma unroll
    for (int j = 0; j < CPT; j += 4) {
        float4 r4 = *(const float4*)&pre[s0 + j];
        float4 i4 = *(const float4*)&pim[s0 + j];
        BSTEP(Br, Bi, r4.x, i4.x);
        BSTEP(Br, Bi, r4.y, i4.y);
        BSTEP(Br, Bi, r4.z, i4.z);
        BSTEP(Br, Bi, r4.w, i4.w);
    }
    smr[t] = Br; smi[t] = Bi;
#pragma unroll
    for (int k = 0; k < LEVELS; k++) {
        int off = 1 << k;
        float2 mm = s_mul[k];
        __syncthreads();
        float lr = 0.f, li = 0.f;
        if (t >= off) { lr = smr[t - off]; li = smi[t - off]; }
        __syncthreads();
        if (t >= off) {
            float nr = fmaf(mm.x, lr, fmaf(-mm.y, li, Br));
            float ni = fmaf(mm.x, li, fmaf( mm.y, lr, Bi));
            Br = nr; Bi = ni;
            smr[t] = Br; smi[t] = Bi;
        }
    }
    __syncthreads();
    float Er = 0.f, Ei = 0.f;
    if (t > 0) { Er = smr[t - 1]; Ei = smi[t - 1]; }
    float* xre = &g_Xc[n * NSEGS];
    float* xim = &g_Xc[(64 + n) * NSEGS];
#pragma unroll
    for (int j = 0; j < CPT; j += 4) {
        float4 r4 = *(const float4*)&pre[s0 + j];
        float4 i4 = *(const float4*)&pim[s0 + j];
        float4 orv, oiv;
        orv.x = Er; oiv.x = Ei; BSTEP(Er, Ei, r4.x, i4.x);
        orv.y = Er; oiv.y = Ei; BSTEP(Er, Ei, r4.y, i4.y);
        orv.z = Er; oiv.z = Ei; BSTEP(Er, Ei, r4.z, i4.z);
        orv.w = Er; oiv.w = Ei; BSTEP(Er, Ei, r4.w, i4.w);
        *(float4*)&xre[s0 + j] = orv;
        *(float4*)&xim[s0 + j] = oiv;
    }
}

// ---------------- kC: Y = Mt^T @ [U;Xc], 8-warp K-split, 16 acc/thread ----------------
// grid = 512 blocks (16 segs) x 256 thr. Warp w: k in [20w, 20w+20); thread: row=lane.
// Reduction buffer aliases sMt (dead after the k-loop) -> 33 KB smem, 6 blocks/SM.
__global__ void __launch_bounds__(KC_THR) kC_ygemm(const float* __restrict__ u,
                                                   float* __restrict__ y) {
    __shared__ float sMt[160 * 32];      // 20 KB; reused as sRed[8*512] after compute
    __shared__ float sR[160 * RSTR];     // 12.8 KB
    int t = threadIdx.x, b = blockIdx.x;
    int ss = b * KC_CHUNK;

    {   // stage Mt, coalesced float4
        const float4* src = (const float4*)g_Mt;
        float4* dst = (float4*)sMt;
        for (int i = t; i < 1280; i += KC_THR) dst[i] = src[i];
    }
    // R rows 0..31 = U^T
    for (int i = t; i < 512; i += KC_THR) {
        int seg = i >> 5, k = i & 31;
        sR[k * RSTR + seg] = u[ss * 32 + i];
    }
    // R rows 32..159 = Xc rows 0..127, float4 both sides
    for (int i = t; i < 512; i += KC_THR) {
        int rr = i >> 2, c4 = i & 3;
        float4 v = *(const float4*)&g_Xc[rr * NSEGS + ss + 4 * c4];
        *(float4*)&sR[(32 + rr) * RSTR + 4 * c4] = v;
    }
    __syncthreads();

    int lane = t & 31, w = t >> 5;       // 8 warps
    int kbase = w * 20;
    float acc[16];
#pragma unroll
    for (int j = 0; j < 16; j++) acc[j] = 0.f;
#pragma unroll 5
    for (int kk = 0; kk < 20; kk++) {
        int k = kbase + kk;
        float  mv = sMt[k * 32 + lane];                 // conflict-free LDS.32
        float4 r0 = *(const float4*)&sR[k * RSTR];      // broadcasts
        float4 r1 = *(const float4*)&sR[k * RSTR + 4];
        float4 r2 = *(const float4*)&sR[k * RSTR + 8];
        float4 r3 = *(const float4*)&sR[k * RSTR + 12];
        acc[0]  = fmaf(mv, r0.x, acc[0]);  acc[1]  = fmaf(mv, r0.y, acc[1]);
        acc[2]  = fmaf(mv, r0.z, acc[2]);  acc[3]  = fmaf(mv, r0.w, acc[3]);
        acc[4]  = fmaf(mv, r1.x, acc[4]);  acc[5]  = fmaf(mv, r1.y, acc[5]);
        acc[6]  = fmaf(mv, r1.z, acc[6]);  acc[7]  = fmaf(mv, r1.w, acc[7]);
        acc[8]  = fmaf(mv, r2.x, acc[8]);  acc[9]  = fmaf(mv, r2.y, acc[9]);
        acc[10] = fmaf(mv, r2.z, acc[10]); acc[11] = fmaf(mv, r2.w, acc[11]);
        acc[12] = fmaf(mv, r3.x, acc[12]); acc[13] = fmaf(mv, r3.y, acc[13]);
        acc[14] = fmaf(mv, r3.z, acc[14]); acc[15] = fmaf(mv, r3.w, acc[15]);
    }
    __syncthreads();                     // everyone done READING sMt
    float* sRed = sMt;                   // alias: 8*512 floats
#pragma unroll
    for (int j = 0; j < 16; j++) sRed[w * 512 + j * 32 + lane] = acc[j];
    __syncthreads();

    for (int i = t; i < 512; i += KC_THR) {   // fixed-order 8-way sum, coalesced write
        float s = ((sRed[i]        + sRed[512 + i])  + (sRed[1024 + i] + sRed[1536 + i]))
                + ((sRed[2048 + i] + sRed[2560 + i]) + (sRed[3072 + i] + sRed[3584 + i]));
        y[ss * 32 + i] = s;
    }
}

// ---------------- host: 3 kernel nodes ----------------
extern "C" void kernel_launch(void* const* d_in, const int* in_sizes, int n_in,
                              void* d_out, int out_size) {
    const float* u = 0; const float* A_re = 0; const float* A_im = 0;
    const float* C = 0; const float* D = 0; const float* log_step = 0;
    for (int i = 0; i < n_in; i++) {
        int sz = in_sizes[i];
        const float* p = (const float*)d_in[i];
        if (sz == LSEQ)            { if (!u) u = p; }
        else if (sz == 2 * NMODES) { if (!C) C = p; }
        else if (sz == NMODES)     { if (!A_re) A_re = p; else A_im = p; }
        else if (sz == 1)          { if (!D) D = p; else log_step = p; }
    }
    float* y = (float*)d_out;

    kA_pgemm<<<KA_GRID, KA_THR>>>(u, A_re, A_im, log_step);
    kB_scan<<<NMODES, SCAN_T>>>(A_re, A_im, C, D, log_step);
    kC_ygemm<<<KC_GRID, KC_THR>>>(u, y);
}